// round 8
// baseline (speedup 1.0000x reference)
#include <cuda_runtime.h>
#include <cuda_bf16.h>
#include <cstdint>

#define N_ATOMS   50000
#define NUM_ELEM  10
#define LMAX      3
#define SH_DIM    16
#define CIN       128
#define COUT      128
#define TILE_M    64
#define NSEG      (NUM_ELEM * (LMAX + 1))
// tiles: sum_seg ceil(rows/64) <= 50000*16/64 + 40 = 12540
#define GRID_GEMM 12560
#define AS_W      132   // tf32 words per A row (128 + 4 pad)

__device__ int   g_counts[NUM_ELEM];
__device__ int   g_cursor[NUM_ELEM];
__device__ int   g_offsets[NUM_ELEM];
__device__ int   g_species[N_ATOMS];
__device__ int   g_order[N_ATOMS];
__device__ int   g_tile_prefix[NSEG + 1];
// W packed in tf32 mma B-fragment layout:
// [seg][ks16(8)][nt(16)][lane(32)] -> uint4 {s0.b0, s0.b1, s1.b0, s1.b1}
__device__ uint4 g_wpack[NSEG * 4096];

// ---------------- helpers ----------------

__device__ __forceinline__ unsigned f2tf32(float v) {
    unsigned u;
    asm("cvt.rna.tf32.f32 %0, %1;" : "=r"(u) : "f"(v));
    return u;
}

__device__ __forceinline__ void mma_tf32(float* c, unsigned a0, unsigned a1,
                                         unsigned a2, unsigned a3,
                                         unsigned b0, unsigned b1) {
    asm volatile(
        "mma.sync.aligned.m16n8k8.row.col.f32.tf32.tf32.f32 "
        "{%0,%1,%2,%3}, {%4,%5,%6,%7}, {%8,%9}, {%0,%1,%2,%3};\n"
        : "+f"(c[0]), "+f"(c[1]), "+f"(c[2]), "+f"(c[3])
        : "r"(a0), "r"(a1), "r"(a2), "r"(a3), "r"(b0), "r"(b1));
}

// ---------------- prep kernels ----------------

__global__ void k_init() {
    int t = threadIdx.x;
    if (t < NUM_ELEM) { g_counts[t] = 0; g_cursor[t] = 0; }
}

__global__ void k_hist(const float* __restrict__ y) {
    __shared__ int cnt[NUM_ELEM];
    int tid = threadIdx.x;
    if (tid < NUM_ELEM) cnt[tid] = 0;
    __syncthreads();
    int n = blockIdx.x * blockDim.x + tid;
    if (n < N_ATOMS) {
        const float* yr = y + (long)n * NUM_ELEM;
        float best = yr[0]; int s = 0;
#pragma unroll
        for (int e = 1; e < NUM_ELEM; e++) {
            float v = yr[e];
            if (v > best) { best = v; s = e; }
        }
        g_species[n] = s;
        atomicAdd(&cnt[s], 1);
    }
    __syncthreads();
    if (tid < NUM_ELEM && cnt[tid] > 0) atomicAdd(&g_counts[tid], cnt[tid]);
}

__global__ void k_scan() {
    if (threadIdx.x == 0) {
        int off = 0;
        for (int e = 0; e < NUM_ELEM; e++) { g_offsets[e] = off; off += g_counts[e]; }
        int tp = 0, seg = 0;
        g_tile_prefix[0] = 0;
        for (int e = 0; e < NUM_ELEM; e++)
            for (int l = 0; l <= LMAX; l++) {
                int rows = g_counts[e] * (2 * l + 1);
                tp += (rows + TILE_M - 1) / TILE_M;
                g_tile_prefix[++seg] = tp;
            }
    }
}

__global__ void k_scatter() {
    __shared__ int cnt[NUM_ELEM];
    __shared__ int base[NUM_ELEM];
    int tid = threadIdx.x;
    if (tid < NUM_ELEM) cnt[tid] = 0;
    __syncthreads();
    int n = blockIdx.x * blockDim.x + tid;
    int s = -1, myrank = 0;
    if (n < N_ATOMS) {
        s = g_species[n];
        myrank = atomicAdd(&cnt[s], 1);
    }
    __syncthreads();
    if (tid < NUM_ELEM) base[tid] = cnt[tid] ? atomicAdd(&g_cursor[tid], cnt[tid]) : 0;
    __syncthreads();
    if (n < N_ATOMS) g_order[g_offsets[s] + base[s] + myrank] = n;
}

// Pack W[e][l] into tf32 mma B-fragment layout.
// For k8-step s of K16 block ks, thread lane (g=lane>>2, tig=lane&3) of n-tile
// nt needs b0 = W[ks*16+s*8+tig][n], b1 = W[ks*16+s*8+tig+4][n], n = nt*8+g.
__global__ void k_wpack(const float* __restrict__ w) {
    int idx = blockIdx.x * blockDim.x + threadIdx.x;
    if (idx >= NSEG * 4096) return;
    int seg = idx >> 12;
    int rem = idx & 4095;
    int ks = rem >> 9;
    int nt = (rem >> 5) & 15;
    int t  = rem & 31;
    int tig = t & 3;
    int n  = nt * 8 + (t >> 2);
    const float* W = w + (long)seg * CIN * COUT;
    int k0 = ks * 16;
    unsigned b00 = f2tf32(W[(k0 + tig         ) * COUT + n]);
    unsigned b01 = f2tf32(W[(k0 + tig + 4     ) * COUT + n]);
    unsigned b10 = f2tf32(W[(k0 + 8 + tig     ) * COUT + n]);
    unsigned b11 = f2tf32(W[(k0 + 8 + tig + 4 ) * COUT + n]);
    g_wpack[idx] = make_uint4(b00, b01, b10, b11);
}

// ---------------- tf32 tensor-core tile GEMM ----------------
// CTA: 64 gathered rows x full W[e,l] 128x128. 256 threads / 8 warps,
// 2 CTAs/SM (SMEM ~97KB). Warp w: m-tile (w&3) (16 rows), n-half (w>>2)
// (8 n-tiles = 64 cols). A staged in SMEM pre-converted to tf32 (coalesced
// float4 gather, convert once); mainloop = conflict-free LDS.32 + LDS.128 + HMMA.

#define SMEM_BYTES (TILE_M * AS_W * 4 + 4096 * 16 + TILE_M * 4)

__global__ __launch_bounds__(256, 2)
void k_gemm(const float* __restrict__ x, float* __restrict__ out) {
    extern __shared__ char smem_raw[];
    unsigned* As   = (unsigned*)smem_raw;                       // [64][132] tf32 bits
    uint4* Bs      = (uint4*)(smem_raw + TILE_M * AS_W * 4);    // [8][16][32]
    int*   rowbase = (int*)(Bs + 4096);

    int t = blockIdx.x;
    if (t >= g_tile_prefix[NSEG]) return;
    int seg = 0;
    while (g_tile_prefix[seg + 1] <= t) seg++;
    int e = seg >> 2, l = seg & 3;
    int row0 = (t - g_tile_prefix[seg]) * TILE_M;
    int R = 2 * l + 1;
    int Mseg = g_counts[e] * R;
    int offe = g_offsets[e];
    int tid = threadIdx.x;

    // per-row x base offsets
    if (tid < TILE_M) {
        int r = row0 + tid;
        int rb = -1;
        if (r < Mseg) {
            int atom = g_order[offe + r / R];
            rb = (atom * SH_DIM + l * l + r % R) * CIN;
        }
        rowbase[tid] = rb;
    }

    // B fill: 64KB linear copy of pre-packed frags (hits L2; W is 5.2MB total)
    {
        const uint4* wp = g_wpack + seg * 4096;
#pragma unroll
        for (int i = 0; i < 16; i++) Bs[tid + i * 256] = wp[tid + i * 256];
    }
    __syncthreads();   // rowbase ready for A gather

    // A fill: 4 threads/row, 32 cols each; coalesced float4 loads, convert to
    // tf32 once, store bits to SMEM. Invalid rows -> zeros (no mainloop preds).
    {
        int m = tid >> 2, q = tid & 3;
        int rb = rowbase[m];
        unsigned* dst = As + m * AS_W + q * 32;
        if (rb >= 0) {
            const float4* src = (const float4*)(x + rb + q * 32);
#pragma unroll
            for (int i = 0; i < 8; i++) {
                float4 v = src[i];
                dst[i * 4 + 0] = f2tf32(v.x);
                dst[i * 4 + 1] = f2tf32(v.y);
                dst[i * 4 + 2] = f2tf32(v.z);
                dst[i * 4 + 3] = f2tf32(v.w);
            }
        } else {
#pragma unroll
            for (int i = 0; i < 32; i++) dst[i] = 0u;
        }
    }
    __syncthreads();

    int w    = tid >> 5;
    int lane = tid & 31;
    int g    = lane >> 2;
    int tig  = lane & 3;
    int mt   = (w & 3) * 16;        // m-tile row base
    int ntb  = (w >> 2) * 8;        // 8 n-tiles (64 cols)

    const unsigned* Ar0 = As + (mt + g) * AS_W;       // row g
    const unsigned* Ar1 = As + (mt + g + 8) * AS_W;   // row g+8

    float acc[8][4];
#pragma unroll
    for (int nt = 0; nt < 8; nt++)
#pragma unroll
        for (int i = 0; i < 4; i++) acc[nt][i] = 0.f;

#pragma unroll
    for (int ks = 0; ks < 8; ks++) {
        int c = ks * 16 + tig;
        // A fragments for both k8 steps (conflict-free LDS.32: bank=4g+c)
        unsigned a00 = Ar0[c];      unsigned a01 = Ar1[c];
        unsigned a02 = Ar0[c + 4];  unsigned a03 = Ar1[c + 4];
        unsigned a10 = Ar0[c + 8];  unsigned a11 = Ar1[c + 8];
        unsigned a12 = Ar0[c + 12]; unsigned a13 = Ar1[c + 12];
#pragma unroll
        for (int ntl = 0; ntl < 8; ntl++) {
            uint4 B = Bs[ks * 512 + (ntb + ntl) * 32 + lane];
            mma_tf32(acc[ntl], a00, a01, a02, a03, B.x, B.y);
            mma_tf32(acc[ntl], a10, a11, a12, a13, B.z, B.w);
        }
    }

    const float scale = 0.08838834764831845f;  // 1/sqrt(128)
    int rlo = rowbase[mt + g];
    int rhi = rowbase[mt + g + 8];
#pragma unroll
    for (int ntl = 0; ntl < 8; ntl++) {
        int col = (ntb + ntl) * 8 + 2 * tig;
        if (rlo >= 0)
            *(float2*)(out + rlo + col) =
                make_float2(acc[ntl][0] * scale, acc[ntl][1] * scale);
        if (rhi >= 0)
            *(float2*)(out + rhi + col) =
                make_float2(acc[ntl][2] * scale, acc[ntl][3] * scale);
    }
}

// ---------------- launch ----------------

extern "C" void kernel_launch(void* const* d_in, const int* in_sizes, int n_in,
                              void* d_out, int out_size) {
    const float* x = (const float*)d_in[0];   // [N, 16, 128]
    const float* y = (const float*)d_in[1];   // [N, 10]
    const float* w = (const float*)d_in[2];   // [10, 4, 128, 128]
    float* out = (float*)d_out;               // [N, 16, 128]

    cudaFuncSetAttribute(k_gemm, cudaFuncAttributeMaxDynamicSharedMemorySize,
                         SMEM_BYTES);

    k_init<<<1, 32>>>();
    k_hist<<<(N_ATOMS + 255) / 256, 256>>>(y);
    k_scan<<<1, 32>>>();
    k_scatter<<<(N_ATOMS + 255) / 256, 256>>>();
    k_wpack<<<(NSEG * 4096 + 255) / 256, 256>>>(w);
    k_gemm<<<GRID_GEMM, 256, SMEM_BYTES>>>(x, out);
}

// round 9
// speedup vs baseline: 1.9629x; 1.9629x over previous
#include <cuda_runtime.h>
#include <cuda_bf16.h>
#include <cstdint>

#define N_ATOMS   50000
#define NUM_ELEM  10
#define LMAX      3
#define SH_DIM    16
#define CIN       128
#define COUT      128
#define TILE_M    128
#define NSEG      (NUM_ELEM * (LMAX + 1))
// tiles: sum_seg ceil(rows/128) <= 50000*16/128 + 40 = 6290
#define GRID_GEMM 6290
#define PAN_W     20          // fp32 words per panel row (16 + 4 pad)
#define PAN_BYTES (TILE_M * PAN_W * 4)   // 10240
#define SM_B      (2 * PAN_BYTES)        // 20480
#define SM_ROWB   (SM_B + 65536)         // 86016
#define SMEM_BYTES (SM_ROWB + TILE_M * 4)

__device__ int   g_counts[NUM_ELEM];
__device__ int   g_cursor[NUM_ELEM];
__device__ int   g_offsets[NUM_ELEM];
__device__ int   g_species[N_ATOMS];
__device__ int   g_order[N_ATOMS];
__device__ int   g_tile_prefix[NSEG + 1];
// W packed in tf32 mma B-fragment layout:
// [seg][ks16(8)][nt(16)][lane(32)] -> uint4 {s0.b0, s0.b1, s1.b0, s1.b1}
__device__ uint4 g_wpack[NSEG * 4096];

// ---------------- helpers ----------------

__device__ __forceinline__ unsigned f2tf32(float v) {
    unsigned u;
    asm("cvt.rna.tf32.f32 %0, %1;" : "=r"(u) : "f"(v));
    return u;
}

__device__ __forceinline__ void mma_tf32(float* c, unsigned a0, unsigned a1,
                                         unsigned a2, unsigned a3,
                                         unsigned b0, unsigned b1) {
    asm volatile(
        "mma.sync.aligned.m16n8k8.row.col.f32.tf32.tf32.f32 "
        "{%0,%1,%2,%3}, {%4,%5,%6,%7}, {%8,%9}, {%0,%1,%2,%3};\n"
        : "+f"(c[0]), "+f"(c[1]), "+f"(c[2]), "+f"(c[3])
        : "r"(a0), "r"(a1), "r"(a2), "r"(a3), "r"(b0), "r"(b1));
}

__device__ __forceinline__ void cp16(uint32_t dst, const void* src, int srcsize) {
    asm volatile("cp.async.cg.shared.global [%0], [%1], 16, %2;"
                 :: "r"(dst), "l"(src), "r"(srcsize));
}

// ---------------- prep kernels ----------------

__global__ void k_init() {
    int t = threadIdx.x;
    if (t < NUM_ELEM) { g_counts[t] = 0; g_cursor[t] = 0; }
}

__global__ void k_hist(const float* __restrict__ y) {
    __shared__ int cnt[NUM_ELEM];
    int tid = threadIdx.x;
    if (tid < NUM_ELEM) cnt[tid] = 0;
    __syncthreads();
    int n = blockIdx.x * blockDim.x + tid;
    if (n < N_ATOMS) {
        const float* yr = y + (long)n * NUM_ELEM;
        float best = yr[0]; int s = 0;
#pragma unroll
        for (int e = 1; e < NUM_ELEM; e++) {
            float v = yr[e];
            if (v > best) { best = v; s = e; }
        }
        g_species[n] = s;
        atomicAdd(&cnt[s], 1);
    }
    __syncthreads();
    if (tid < NUM_ELEM && cnt[tid] > 0) atomicAdd(&g_counts[tid], cnt[tid]);
}

__global__ void k_scan() {
    if (threadIdx.x == 0) {
        int off = 0;
        for (int e = 0; e < NUM_ELEM; e++) { g_offsets[e] = off; off += g_counts[e]; }
        int tp = 0, seg = 0;
        g_tile_prefix[0] = 0;
        for (int e = 0; e < NUM_ELEM; e++)
            for (int l = 0; l <= LMAX; l++) {
                int rows = g_counts[e] * (2 * l + 1);
                tp += (rows + TILE_M - 1) / TILE_M;
                g_tile_prefix[++seg] = tp;
            }
    }
}

__global__ void k_scatter() {
    __shared__ int cnt[NUM_ELEM];
    __shared__ int base[NUM_ELEM];
    int tid = threadIdx.x;
    if (tid < NUM_ELEM) cnt[tid] = 0;
    __syncthreads();
    int n = blockIdx.x * blockDim.x + tid;
    int s = -1, myrank = 0;
    if (n < N_ATOMS) {
        s = g_species[n];
        myrank = atomicAdd(&cnt[s], 1);
    }
    __syncthreads();
    if (tid < NUM_ELEM) base[tid] = cnt[tid] ? atomicAdd(&g_cursor[tid], cnt[tid]) : 0;
    __syncthreads();
    if (n < N_ATOMS) g_order[g_offsets[s] + base[s] + myrank] = n;
}

// Pack W[e][l] into tf32 mma B-fragment layout.
__global__ void k_wpack(const float* __restrict__ w) {
    int idx = blockIdx.x * blockDim.x + threadIdx.x;
    if (idx >= NSEG * 4096) return;
    int seg = idx >> 12;
    int rem = idx & 4095;
    int ks = rem >> 9;
    int nt = (rem >> 5) & 15;
    int t  = rem & 31;
    int tig = t & 3;
    int n  = nt * 8 + (t >> 2);
    const float* W = w + (long)seg * CIN * COUT;
    int k0 = ks * 16;
    unsigned b00 = f2tf32(W[(k0 + tig         ) * COUT + n]);
    unsigned b01 = f2tf32(W[(k0 + tig + 4     ) * COUT + n]);
    unsigned b10 = f2tf32(W[(k0 + 8 + tig     ) * COUT + n]);
    unsigned b11 = f2tf32(W[(k0 + 8 + tig + 4 ) * COUT + n]);
    g_wpack[idx] = make_uint4(b00, b01, b10, b11);
}

// ---------------- tf32 tensor-core tile GEMM ----------------
// CTA: 128 gathered rows x full W[e,l] 128x128. 256 threads / 8 warps,
// 2 CTAs/SM (SMEM ~85KB). Warp w: m-block (w&3)*32 (2 m-tiles), n-half
// (w>>2)*64 (8 n-tiles). A k-panels (128x16 fp32) double-buffered in SMEM
// via cp.async.cg (L1-bypass, zero-fill OOB rows), overlapping the mainloop.

__global__ __launch_bounds__(256, 2)
void k_gemm(const float* __restrict__ x, float* __restrict__ out) {
    extern __shared__ char smraw[];
    float* Apan    = (float*)smraw;                 // [2][128][20]
    uint4* Bs      = (uint4*)(smraw + SM_B);        // [8][16][32]
    int*   rowbase = (int*)(smraw + SM_ROWB);

    int t = blockIdx.x;
    if (t >= g_tile_prefix[NSEG]) return;
    int seg = 0;
    while (g_tile_prefix[seg + 1] <= t) seg++;
    int e = seg >> 2, l = seg & 3;
    int row0 = (t - g_tile_prefix[seg]) * TILE_M;
    int R = 2 * l + 1;
    int Mseg = g_counts[e] * R;
    int offe = g_offsets[e];
    int tid = threadIdx.x;

    // per-row x base offsets
    if (tid < TILE_M) {
        int r = row0 + tid;
        int rb = -1;
        if (r < Mseg) {
            int atom = g_order[offe + r / R];
            rb = (atom * SH_DIM + l * l + r % R) * CIN;
        }
        rowbase[tid] = rb;
    }

    // B fill: 64KB linear copy of pre-packed frags (from L2; W pack is 2.6MB)
    {
        const uint4* wp = g_wpack + seg * 4096;
#pragma unroll
        for (int i = 0; i < 16; i++) Bs[tid + i * 256] = wp[tid + i * 256];
    }
    __syncthreads();

    // A-panel gather setup: thread handles rows (tid>>2) and 64+(tid>>2),
    // col-quad q = tid&3 (16B each) -> per stage 2 cp.async per thread.
    int grow = tid >> 2, q = tid & 3;
    int rb_g0 = rowbase[grow];
    int rb_g1 = rowbase[64 + grow];
    const float* s0base = x + (rb_g0 < 0 ? 0 : rb_g0) + q * 4;
    const float* s1base = x + (rb_g1 < 0 ? 0 : rb_g1) + q * 4;
    int z0 = rb_g0 < 0 ? 0 : 16;
    int z1 = rb_g1 < 0 ? 0 : 16;
    uint32_t sb = (uint32_t)__cvta_generic_to_shared(Apan);
    uint32_t d0 = sb + (grow * PAN_W + q * 4) * 4;
    uint32_t d1 = sb + ((64 + grow) * PAN_W + q * 4) * 4;

    // prefetch panel 0
    cp16(d0, s0base, z0);
    cp16(d1, s1base, z1);
    asm volatile("cp.async.commit_group;" ::: "memory");

    int w    = tid >> 5;
    int lane = tid & 31;
    int g    = lane >> 2;
    int tig  = lane & 3;
    int mrow0 = (w & 3) * 32;       // 2 m-tiles
    int ntb   = (w >> 2) * 8;       // 8 n-tiles (64 cols)

    float acc[2][8][4];
#pragma unroll
    for (int m = 0; m < 2; m++)
#pragma unroll
        for (int nt = 0; nt < 8; nt++)
#pragma unroll
            for (int i = 0; i < 4; i++) acc[m][nt][i] = 0.f;

#pragma unroll
    for (int ks = 0; ks < 8; ks++) {
        if (ks < 7) {
            uint32_t off = ((ks + 1) & 1) * PAN_BYTES;
            cp16(d0 + off, s0base + (ks + 1) * 16, z0);
            cp16(d1 + off, s1base + (ks + 1) * 16, z1);
            asm volatile("cp.async.commit_group;" ::: "memory");
            asm volatile("cp.async.wait_group 1;" ::: "memory");
        } else {
            asm volatile("cp.async.wait_group 0;" ::: "memory");
        }
        __syncthreads();   // panel ks visible to all warps

        const float* A = Apan + (ks & 1) * (PAN_BYTES / 4);
#pragma unroll
        for (int m = 0; m < 2; m++) {
            const float* Ar0 = A + (mrow0 + m * 16 + g) * PAN_W;
            const float* Ar1 = Ar0 + 8 * PAN_W;
            unsigned a00 = f2tf32(Ar0[tig]);
            unsigned a01 = f2tf32(Ar1[tig]);
            unsigned a02 = f2tf32(Ar0[tig + 4]);
            unsigned a03 = f2tf32(Ar1[tig + 4]);
            unsigned a10 = f2tf32(Ar0[tig + 8]);
            unsigned a11 = f2tf32(Ar1[tig + 8]);
            unsigned a12 = f2tf32(Ar0[tig + 12]);
            unsigned a13 = f2tf32(Ar1[tig + 12]);
#pragma unroll
            for (int ntl = 0; ntl < 8; ntl++) {
                uint4 B = Bs[ks * 512 + (ntb + ntl) * 32 + lane];
                mma_tf32(acc[m][ntl], a00, a01, a02, a03, B.x, B.y);
                mma_tf32(acc[m][ntl], a10, a11, a12, a13, B.z, B.w);
            }
        }
        __syncthreads();   // protect buffer (ks&1) before it is overwritten
    }

    const float scale = 0.08838834764831845f;  // 1/sqrt(128)
#pragma unroll
    for (int m = 0; m < 2; m++) {
        int rlo = rowbase[mrow0 + m * 16 + g];
        int rhi = rowbase[mrow0 + m * 16 + g + 8];
#pragma unroll
        for (int ntl = 0; ntl < 8; ntl++) {
            int col = (ntb + ntl) * 8 + 2 * tig;
            if (rlo >= 0)
                *(float2*)(out + rlo + col) =
                    make_float2(acc[m][ntl][0] * scale, acc[m][ntl][1] * scale);
            if (rhi >= 0)
                *(float2*)(out + rhi + col) =
                    make_float2(acc[m][ntl][2] * scale, acc[m][ntl][3] * scale);
        }
    }
}

// ---------------- launch ----------------

extern "C" void kernel_launch(void* const* d_in, const int* in_sizes, int n_in,
                              void* d_out, int out_size) {
    const float* x = (const float*)d_in[0];   // [N, 16, 128]
    const float* y = (const float*)d_in[1];   // [N, 10]
    const float* w = (const float*)d_in[2];   // [10, 4, 128, 128]
    float* out = (float*)d_out;               // [N, 16, 128]

    cudaFuncSetAttribute(k_gemm, cudaFuncAttributeMaxDynamicSharedMemorySize,
                         SMEM_BYTES);

    k_init<<<1, 32>>>();
    k_hist<<<(N_ATOMS + 255) / 256, 256>>>(y);
    k_scan<<<1, 32>>>();
    k_scatter<<<(N_ATOMS + 255) / 256, 256>>>();
    k_wpack<<<(NSEG * 4096 + 255) / 256, 256>>>(w);
    k_gemm<<<GRID_GEMM, 256, SMEM_BYTES>>>(x, out);
}

// round 10
// speedup vs baseline: 2.0887x; 1.0640x over previous
#include <cuda_runtime.h>
#include <cuda_bf16.h>
#include <cstdint>

#define N_ATOMS   50000
#define NUM_ELEM  10
#define LMAX      3
#define SH_DIM    16
#define CIN       128
#define COUT      128
#define TILE_M    128
#define NSEG      (NUM_ELEM * (LMAX + 1))
// tiles: sum_seg ceil(rows/128) <= 50000*16/128 + 40 = 6290
#define GRID_GEMM 6290
#define PAN_W     20                      // fp32 words per panel row (16 + 4 pad)
#define PAN_BYTES (TILE_M * PAN_W * 4)    // 10240
#define NSTAGE    4
#define SM_B      (NSTAGE * PAN_BYTES)    // 40960
#define SM_ROWB   (SM_B + 65536)          // 106496
#define SMEM_BYTES (SM_ROWB + TILE_M * 4)

__device__ int   g_counts[NUM_ELEM];
__device__ int   g_cursor[NUM_ELEM];
__device__ int   g_offsets[NUM_ELEM];
__device__ int   g_species[N_ATOMS];
__device__ int   g_order[N_ATOMS];
__device__ int   g_tile_prefix[NSEG + 1];
// W packed in tf32 mma B-fragment layout:
// [seg][ks16(8)][nt(16)][lane(32)] -> uint4 {s0.b0, s0.b1, s1.b0, s1.b1}
__device__ uint4 g_wpack[NSEG * 4096];

// ---------------- helpers ----------------

__device__ __forceinline__ unsigned f2tf32(float v) {
    unsigned u;
    asm("cvt.rna.tf32.f32 %0, %1;" : "=r"(u) : "f"(v));
    return u;
}

__device__ __forceinline__ void mma_tf32(float* c, unsigned a0, unsigned a1,
                                         unsigned a2, unsigned a3,
                                         unsigned b0, unsigned b1) {
    asm volatile(
        "mma.sync.aligned.m16n8k8.row.col.f32.tf32.tf32.f32 "
        "{%0,%1,%2,%3}, {%4,%5,%6,%7}, {%8,%9}, {%0,%1,%2,%3};\n"
        : "+f"(c[0]), "+f"(c[1]), "+f"(c[2]), "+f"(c[3])
        : "r"(a0), "r"(a1), "r"(a2), "r"(a3), "r"(b0), "r"(b1));
}

__device__ __forceinline__ void cp16(uint32_t dst, const void* src, int srcsize) {
    asm volatile("cp.async.cg.shared.global [%0], [%1], 16, %2;"
                 :: "r"(dst), "l"(src), "r"(srcsize));
}

// ---------------- prep kernels ----------------

__global__ void k_init() {
    int t = threadIdx.x;
    if (t < NUM_ELEM) { g_counts[t] = 0; g_cursor[t] = 0; }
}

__global__ void k_hist(const float* __restrict__ y) {
    __shared__ int cnt[NUM_ELEM];
    int tid = threadIdx.x;
    if (tid < NUM_ELEM) cnt[tid] = 0;
    __syncthreads();
    int n = blockIdx.x * blockDim.x + tid;
    if (n < N_ATOMS) {
        const float* yr = y + (long)n * NUM_ELEM;
        float best = yr[0]; int s = 0;
#pragma unroll
        for (int e = 1; e < NUM_ELEM; e++) {
            float v = yr[e];
            if (v > best) { best = v; s = e; }
        }
        g_species[n] = s;
        atomicAdd(&cnt[s], 1);
    }
    __syncthreads();
    if (tid < NUM_ELEM && cnt[tid] > 0) atomicAdd(&g_counts[tid], cnt[tid]);
}

__global__ void k_scan() {
    if (threadIdx.x == 0) {
        int off = 0;
        for (int e = 0; e < NUM_ELEM; e++) { g_offsets[e] = off; off += g_counts[e]; }
        int tp = 0, seg = 0;
        g_tile_prefix[0] = 0;
        for (int e = 0; e < NUM_ELEM; e++)
            for (int l = 0; l <= LMAX; l++) {
                int rows = g_counts[e] * (2 * l + 1);
                tp += (rows + TILE_M - 1) / TILE_M;
                g_tile_prefix[++seg] = tp;
            }
    }
}

__global__ void k_scatter() {
    __shared__ int cnt[NUM_ELEM];
    __shared__ int base[NUM_ELEM];
    int tid = threadIdx.x;
    if (tid < NUM_ELEM) cnt[tid] = 0;
    __syncthreads();
    int n = blockIdx.x * blockDim.x + tid;
    int s = -1, myrank = 0;
    if (n < N_ATOMS) {
        s = g_species[n];
        myrank = atomicAdd(&cnt[s], 1);
    }
    __syncthreads();
    if (tid < NUM_ELEM) base[tid] = cnt[tid] ? atomicAdd(&g_cursor[tid], cnt[tid]) : 0;
    __syncthreads();
    if (n < N_ATOMS) g_order[g_offsets[s] + base[s] + myrank] = n;
}

// Pack W[e][l] into tf32 mma B-fragment layout.
__global__ void k_wpack(const float* __restrict__ w) {
    int idx = blockIdx.x * blockDim.x + threadIdx.x;
    if (idx >= NSEG * 4096) return;
    int seg = idx >> 12;
    int rem = idx & 4095;
    int ks = rem >> 9;
    int nt = (rem >> 5) & 15;
    int t  = rem & 31;
    int tig = t & 3;
    int n  = nt * 8 + (t >> 2);
    const float* W = w + (long)seg * CIN * COUT;
    int k0 = ks * 16;
    unsigned b00 = f2tf32(W[(k0 + tig         ) * COUT + n]);
    unsigned b01 = f2tf32(W[(k0 + tig + 4     ) * COUT + n]);
    unsigned b10 = f2tf32(W[(k0 + 8 + tig     ) * COUT + n]);
    unsigned b11 = f2tf32(W[(k0 + 8 + tig + 4 ) * COUT + n]);
    g_wpack[idx] = make_uint4(b00, b01, b10, b11);
}

// ---------------- tf32 tensor-core tile GEMM ----------------
// CTA: 128 gathered rows x full W[e,l] 128x128. 256 threads / 8 warps,
// 2 CTAs/SM (SMEM ~106KB). Warp w: m-block (w&3)*32 (2 m-tiles), n-half
// (w>>2)*64 (8 n-tiles). A k-panels (128x16 fp32) in a 4-stage cp.async ring
// (prefetch distance 3), one __syncthreads per k-step.

__global__ __launch_bounds__(256, 2)
void k_gemm(const float* __restrict__ x, float* __restrict__ out) {
    extern __shared__ char smraw[];
    float* Apan    = (float*)smraw;                 // [4][128][20]
    uint4* Bs      = (uint4*)(smraw + SM_B);        // [8][16][32]
    int*   rowbase = (int*)(smraw + SM_ROWB);

    int t = blockIdx.x;
    if (t >= g_tile_prefix[NSEG]) return;
    int seg = 0;
    while (g_tile_prefix[seg + 1] <= t) seg++;
    int e = seg >> 2, l = seg & 3;
    int row0 = (t - g_tile_prefix[seg]) * TILE_M;
    int R = 2 * l + 1;
    int Mseg = g_counts[e] * R;
    int offe = g_offsets[e];
    int tid = threadIdx.x;

    // per-row x base offsets
    if (tid < TILE_M) {
        int r = row0 + tid;
        int rb = -1;
        if (r < Mseg) {
            int atom = g_order[offe + r / R];
            rb = (atom * SH_DIM + l * l + r % R) * CIN;
        }
        rowbase[tid] = rb;
    }

    // B fill: 64KB linear copy of pre-packed frags (L2-resident; pack is 2.6MB)
    {
        const uint4* wp = g_wpack + seg * 4096;
#pragma unroll
        for (int i = 0; i < 16; i++) Bs[tid + i * 256] = wp[tid + i * 256];
    }
    __syncthreads();   // rowbase ready

    // A-panel gather: thread covers rows (tid>>2) and 64+(tid>>2), quad q=tid&3.
    int grow = tid >> 2, q = tid & 3;
    int rb_g0 = rowbase[grow];
    int rb_g1 = rowbase[64 + grow];
    const float* s0base = x + (rb_g0 < 0 ? 0 : rb_g0) + q * 4;
    const float* s1base = x + (rb_g1 < 0 ? 0 : rb_g1) + q * 4;
    int z0 = rb_g0 < 0 ? 0 : 16;
    int z1 = rb_g1 < 0 ? 0 : 16;
    uint32_t sb = (uint32_t)__cvta_generic_to_shared(Apan);
    uint32_t d0 = sb + (grow * PAN_W + q * 4) * 4;
    uint32_t d1 = sb + ((64 + grow) * PAN_W + q * 4) * 4;

    // prefetch panels 0..2 (one commit group each)
#pragma unroll
    for (int p = 0; p < NSTAGE - 1; p++) {
        uint32_t off = p * PAN_BYTES;
        cp16(d0 + off, s0base + p * 16, z0);
        cp16(d1 + off, s1base + p * 16, z1);
        asm volatile("cp.async.commit_group;" ::: "memory");
    }

    int w    = tid >> 5;
    int lane = tid & 31;
    int g    = lane >> 2;
    int tig  = lane & 3;
    int mrow0 = (w & 3) * 32;       // 2 m-tiles
    int ntb   = (w >> 2) * 8;       // 8 n-tiles (64 cols)

    float acc[2][8][4];
#pragma unroll
    for (int m = 0; m < 2; m++)
#pragma unroll
        for (int nt = 0; nt < 8; nt++)
#pragma unroll
            for (int i = 0; i < 4; i++) acc[m][nt][i] = 0.f;

#pragma unroll
    for (int ks = 0; ks < 8; ks++) {
        // panel ks must have arrived: pending groups <= min(2, 7-ks)
        if (ks < 6)      asm volatile("cp.async.wait_group 2;" ::: "memory");
        else if (ks == 6) asm volatile("cp.async.wait_group 1;" ::: "memory");
        else              asm volatile("cp.async.wait_group 0;" ::: "memory");
        __syncthreads();   // panel visible to all; compute ks-1 done in all warps

        // issue panel ks+3 into ring slot (ks+3)&3 (last read at compute ks-1)
        if (ks < NSTAGE + 4 - NSTAGE + 1 && ks + NSTAGE - 1 < 8) {
            uint32_t off = ((ks + NSTAGE - 1) & (NSTAGE - 1)) * PAN_BYTES;
            cp16(d0 + off, s0base + (ks + NSTAGE - 1) * 16, z0);
            cp16(d1 + off, s1base + (ks + NSTAGE - 1) * 16, z1);
            asm volatile("cp.async.commit_group;" ::: "memory");
        }

        const float* A = Apan + (ks & (NSTAGE - 1)) * (PAN_BYTES / 4);
#pragma unroll
        for (int m = 0; m < 2; m++) {
            const float* Ar0 = A + (mrow0 + m * 16 + g) * PAN_W;
            const float* Ar1 = Ar0 + 8 * PAN_W;
            unsigned a00 = f2tf32(Ar0[tig]);
            unsigned a01 = f2tf32(Ar1[tig]);
            unsigned a02 = f2tf32(Ar0[tig + 4]);
            unsigned a03 = f2tf32(Ar1[tig + 4]);
            unsigned a10 = f2tf32(Ar0[tig + 8]);
            unsigned a11 = f2tf32(Ar1[tig + 8]);
            unsigned a12 = f2tf32(Ar0[tig + 12]);
            unsigned a13 = f2tf32(Ar1[tig + 12]);
#pragma unroll
            for (int ntl = 0; ntl < 8; ntl++) {
                uint4 B = Bs[ks * 512 + (ntb + ntl) * 32 + lane];
                mma_tf32(acc[m][ntl], a00, a01, a02, a03, B.x, B.y);
                mma_tf32(acc[m][ntl], a10, a11, a12, a13, B.z, B.w);
            }
        }
    }

    const float scale = 0.08838834764831845f;  // 1/sqrt(128)
#pragma unroll
    for (int m = 0; m < 2; m++) {
        int rlo = rowbase[mrow0 + m * 16 + g];
        int rhi = rowbase[mrow0 + m * 16 + g + 8];
#pragma unroll
        for (int ntl = 0; ntl < 8; ntl++) {
            int col = (ntb + ntl) * 8 + 2 * tig;
            if (rlo >= 0)
                *(float2*)(out + rlo + col) =
                    make_float2(acc[m][ntl][0] * scale, acc[m][ntl][1] * scale);
            if (rhi >= 0)
                *(float2*)(out + rhi + col) =
                    make_float2(acc[m][ntl][2] * scale, acc[m][ntl][3] * scale);
        }
    }
}

// ---------------- launch ----------------

extern "C" void kernel_launch(void* const* d_in, const int* in_sizes, int n_in,
                              void* d_out, int out_size) {
    const float* x = (const float*)d_in[0];   // [N, 16, 128]
    const float* y = (const float*)d_in[1];   // [N, 10]
    const float* w = (const float*)d_in[2];   // [10, 4, 128, 128]
    float* out = (float*)d_out;               // [N, 16, 128]

    cudaFuncSetAttribute(k_gemm, cudaFuncAttributeMaxDynamicSharedMemorySize,
                         SMEM_BYTES);

    k_init<<<1, 32>>>();
    k_hist<<<(N_ATOMS + 255) / 256, 256>>>(y);
    k_scan<<<1, 32>>>();
    k_scatter<<<(N_ATOMS + 255) / 256, 256>>>();
    k_wpack<<<(NSEG * 4096 + 255) / 256, 256>>>(w);
    k_gemm<<<GRID_GEMM, 256, SMEM_BYTES>>>(x, out);
}

// round 11
// speedup vs baseline: 2.2809x; 1.0920x over previous
#include <cuda_runtime.h>
#include <cuda_bf16.h>
#include <cstdint>

#define N_ATOMS   50000
#define NUM_ELEM  10
#define LMAX      3
#define SH_DIM    16
#define CIN       128
#define COUT      128
#define TILE_M    128
#define NSEG      (NUM_ELEM * (LMAX + 1))
#define GRID_PERS 296                     // 2 CTAs per SM, persistent
#define PAN_W     20                      // fp32 words per panel row (16 + 4 pad)
#define PAN_BYTES (TILE_M * PAN_W * 4)    // 10240
#define NSTAGE    4

// SMEM layout (bytes)
#define SM_APAN   0
#define SM_BS     (NSTAGE * PAN_BYTES)            // 40960
#define SM_ROWB   (SM_BS + 65536)                 // 106496, rowb[2][128] ints
#define SM_PREFIX (SM_ROWB + 1024)                // 107520, 41 ints (pad 176)
#define SM_CNT    (SM_PREFIX + 176)               // 107696, 10 ints
#define SM_OFF    (SM_CNT + 40)                   // 107736, 10 ints
#define SMEM_BYTES (SM_OFF + 40)                  // 107776

__device__ int   g_counts[NUM_ELEM];
__device__ int   g_cursor[NUM_ELEM];
__device__ int   g_offsets[NUM_ELEM];
__device__ int   g_species[N_ATOMS];
__device__ int   g_order[N_ATOMS];
__device__ int   g_tile_prefix[NSEG + 1];
// W packed in tf32 mma B-fragment layout:
// [seg][ks16(8)][nt(16)][lane(32)] -> uint4 {s0.b0, s0.b1, s1.b0, s1.b1}
__device__ uint4 g_wpack[NSEG * 4096];

// ---------------- helpers ----------------

__device__ __forceinline__ unsigned f2tf32(float v) {
    unsigned u;
    asm("cvt.rna.tf32.f32 %0, %1;" : "=r"(u) : "f"(v));
    return u;
}

__device__ __forceinline__ void mma_tf32(float* c, unsigned a0, unsigned a1,
                                         unsigned a2, unsigned a3,
                                         unsigned b0, unsigned b1) {
    asm volatile(
        "mma.sync.aligned.m16n8k8.row.col.f32.tf32.tf32.f32 "
        "{%0,%1,%2,%3}, {%4,%5,%6,%7}, {%8,%9}, {%0,%1,%2,%3};\n"
        : "+f"(c[0]), "+f"(c[1]), "+f"(c[2]), "+f"(c[3])
        : "r"(a0), "r"(a1), "r"(a2), "r"(a3), "r"(b0), "r"(b1));
}

__device__ __forceinline__ void cp16(uint32_t dst, const void* src, int srcsize) {
    asm volatile("cp.async.cg.shared.global [%0], [%1], 16, %2;"
                 :: "r"(dst), "l"(src), "r"(srcsize));
}

// ---------------- prep kernels ----------------

__global__ void k_init() {
    int t = threadIdx.x;
    if (t < NUM_ELEM) { g_counts[t] = 0; g_cursor[t] = 0; }
}

__global__ void k_hist(const float* __restrict__ y) {
    __shared__ int cnt[NUM_ELEM];
    int tid = threadIdx.x;
    if (tid < NUM_ELEM) cnt[tid] = 0;
    __syncthreads();
    int n = blockIdx.x * blockDim.x + tid;
    if (n < N_ATOMS) {
        const float* yr = y + (long)n * NUM_ELEM;
        float best = yr[0]; int s = 0;
#pragma unroll
        for (int e = 1; e < NUM_ELEM; e++) {
            float v = yr[e];
            if (v > best) { best = v; s = e; }
        }
        g_species[n] = s;
        atomicAdd(&cnt[s], 1);
    }
    __syncthreads();
    if (tid < NUM_ELEM && cnt[tid] > 0) atomicAdd(&g_counts[tid], cnt[tid]);
}

__global__ void k_scan() {
    if (threadIdx.x == 0) {
        int off = 0;
        for (int e = 0; e < NUM_ELEM; e++) { g_offsets[e] = off; off += g_counts[e]; }
        int tp = 0, seg = 0;
        g_tile_prefix[0] = 0;
        for (int e = 0; e < NUM_ELEM; e++)
            for (int l = 0; l <= LMAX; l++) {
                int rows = g_counts[e] * (2 * l + 1);
                tp += (rows + TILE_M - 1) / TILE_M;
                g_tile_prefix[++seg] = tp;
            }
    }
}

__global__ void k_scatter() {
    __shared__ int cnt[NUM_ELEM];
    __shared__ int base[NUM_ELEM];
    int tid = threadIdx.x;
    if (tid < NUM_ELEM) cnt[tid] = 0;
    __syncthreads();
    int n = blockIdx.x * blockDim.x + tid;
    int s = -1, myrank = 0;
    if (n < N_ATOMS) {
        s = g_species[n];
        myrank = atomicAdd(&cnt[s], 1);
    }
    __syncthreads();
    if (tid < NUM_ELEM) base[tid] = cnt[tid] ? atomicAdd(&g_cursor[tid], cnt[tid]) : 0;
    __syncthreads();
    if (n < N_ATOMS) g_order[g_offsets[s] + base[s] + myrank] = n;
}

// Pack W[e][l] into tf32 mma B-fragment layout.
__global__ void k_wpack(const float* __restrict__ w) {
    int idx = blockIdx.x * blockDim.x + threadIdx.x;
    if (idx >= NSEG * 4096) return;
    int seg = idx >> 12;
    int rem = idx & 4095;
    int ks = rem >> 9;
    int nt = (rem >> 5) & 15;
    int t  = rem & 31;
    int tig = t & 3;
    int n  = nt * 8 + (t >> 2);
    const float* W = w + (long)seg * CIN * COUT;
    int k0 = ks * 16;
    unsigned b00 = f2tf32(W[(k0 + tig         ) * COUT + n]);
    unsigned b01 = f2tf32(W[(k0 + tig + 4     ) * COUT + n]);
    unsigned b10 = f2tf32(W[(k0 + 8 + tig     ) * COUT + n]);
    unsigned b11 = f2tf32(W[(k0 + 8 + tig + 4 ) * COUT + n]);
    g_wpack[idx] = make_uint4(b00, b01, b10, b11);
}

// ---------------- persistent tf32 tensor-core GEMM ----------------
// 296 persistent CTAs, each owns a contiguous chunk of ~21 tiles (segment-
// sorted). B resident in SMEM across tiles of the same segment; A k-panels in
// a 4-stage cp.async ring; next tile's rowbase+prologue issued BEFORE the
// current tile's epilogue so the DRAM ramp hides behind the stores.

__global__ __launch_bounds__(256, 2)
void k_gemm(const float* __restrict__ x, float* __restrict__ out) {
    extern __shared__ char smraw[];
    float* Apan    = (float*)(smraw + SM_APAN);     // [4][128][20]
    uint4* Bs      = (uint4*)(smraw + SM_BS);       // [8][16][32]
    int*   rowb    = (int*)(smraw + SM_ROWB);       // [2][128]
    int*   spre    = (int*)(smraw + SM_PREFIX);     // [41]
    int*   scnt    = (int*)(smraw + SM_CNT);        // [10]
    int*   soff    = (int*)(smraw + SM_OFF);        // [10]

    int tid = threadIdx.x;
    if (tid <= NSEG) spre[tid] = g_tile_prefix[tid];
    if (tid < NUM_ELEM) { scnt[tid] = g_counts[tid]; soff[tid] = g_offsets[tid]; }
    __syncthreads();

    int ntiles = spre[NSEG];
    int chunk = (ntiles + (int)gridDim.x - 1) / (int)gridDim.x;
    int t0   = blockIdx.x * chunk;
    int tend = min(t0 + chunk, ntiles);
    if (t0 >= tend) return;

    int seg = 0;
    while (spre[seg + 1] <= t0) seg++;

    int w    = tid >> 5;
    int lane = tid & 31;
    int g    = lane >> 2;
    int tig  = lane & 3;
    int mrow0 = (w & 3) * 32;       // 2 m-tiles per warp
    int ntb   = (w >> 2) * 8;       // 8 n-tiles (64 cols)

    // fixed per-thread cp.async SMEM targets: rows (tid>>2), 64+(tid>>2), quad tid&3
    int grow = tid >> 2, q = tid & 3;
    uint32_t sb = (uint32_t)__cvta_generic_to_shared(Apan);
    uint32_t d0 = sb + (grow * PAN_W + q * 4) * 4;
    uint32_t d1 = sb + ((64 + grow) * PAN_W + q * 4) * 4;

    // --- initial segment: fill B ---
    int cur_seg = seg;
    {
        const uint4* wp = g_wpack + seg * 4096;
#pragma unroll
        for (int i = 0; i < 16; i++) Bs[tid + i * 256] = wp[tid + i * 256];
    }
    // --- rowbase for tile t0 into buf 0 ---
    if (tid < TILE_M) {
        int l = seg & 3, e = seg >> 2;
        int R = 2 * l + 1;
        int r = (t0 - spre[seg]) * TILE_M + tid;
        int rb = -1;
        if (r < scnt[e] * R) {
            int atom = g_order[soff[e] + r / R];
            rb = (atom * SH_DIM + l * l + r % R) * CIN;
        }
        rowb[tid] = rb;
    }
    __syncthreads();

    // per-tile gather state (current tile)
    const float* cs0; const float* cs1; int cz0, cz1;
    {
        int rb0 = rowb[grow], rb1 = rowb[64 + grow];
        cs0 = x + (rb0 < 0 ? 0 : rb0) + q * 4;  cz0 = rb0 < 0 ? 0 : 16;
        cs1 = x + (rb1 < 0 ? 0 : rb1) + q * 4;  cz1 = rb1 < 0 ? 0 : 16;
    }
    // prologue for tile t0: panels 0..2
#pragma unroll
    for (int p = 0; p < NSTAGE - 1; p++) {
        uint32_t off = p * PAN_BYTES;
        cp16(d0 + off, cs0 + p * 16, cz0);
        cp16(d1 + off, cs1 + p * 16, cz1);
        asm volatile("cp.async.commit_group;" ::: "memory");
    }

    float acc[2][8][4];
#pragma unroll
    for (int m = 0; m < 2; m++)
#pragma unroll
        for (int nt = 0; nt < 8; nt++)
#pragma unroll
            for (int i = 0; i < 4; i++) acc[m][nt][i] = 0.f;

    const float scale = 0.08838834764831845f;  // 1/sqrt(128)

    for (int t = t0; t < tend; t++) {
        int buf = (t - t0) & 1;
        int* rbuf = rowb + buf * TILE_M;

        // capture this tile's epilogue row offsets
        int rlo0 = rbuf[mrow0 + g],      rhi0 = rbuf[mrow0 + g + 8];
        int rlo1 = rbuf[mrow0 + 16 + g], rhi1 = rbuf[mrow0 + 16 + g + 8];

        // -------- mainloop: 8 k-steps --------
#pragma unroll
        for (int ks = 0; ks < 8; ks++) {
            if (ks < 6)       asm volatile("cp.async.wait_group 2;" ::: "memory");
            else if (ks == 6) asm volatile("cp.async.wait_group 1;" ::: "memory");
            else              asm volatile("cp.async.wait_group 0;" ::: "memory");
            __syncthreads();
            if (ks < 5) {   // keep prefetch distance 3 within this tile
                uint32_t off = ((ks + 3) & (NSTAGE - 1)) * PAN_BYTES;
                cp16(d0 + off, cs0 + (ks + 3) * 16, cz0);
                cp16(d1 + off, cs1 + (ks + 3) * 16, cz1);
                asm volatile("cp.async.commit_group;" ::: "memory");
            }
            const float* A = Apan + (ks & (NSTAGE - 1)) * (PAN_BYTES / 4);
#pragma unroll
            for (int m = 0; m < 2; m++) {
                const float* Ar0 = A + (mrow0 + m * 16 + g) * PAN_W;
                const float* Ar1 = Ar0 + 8 * PAN_W;
                unsigned a00 = f2tf32(Ar0[tig]);
                unsigned a01 = f2tf32(Ar1[tig]);
                unsigned a02 = f2tf32(Ar0[tig + 4]);
                unsigned a03 = f2tf32(Ar1[tig + 4]);
                unsigned a10 = f2tf32(Ar0[tig + 8]);
                unsigned a11 = f2tf32(Ar1[tig + 8]);
                unsigned a12 = f2tf32(Ar0[tig + 12]);
                unsigned a13 = f2tf32(Ar1[tig + 12]);
#pragma unroll
                for (int ntl = 0; ntl < 8; ntl++) {
                    uint4 B = Bs[ks * 512 + (ntb + ntl) * 32 + lane];
                    mma_tf32(acc[m][ntl], a00, a01, a02, a03, B.x, B.y);
                    mma_tf32(acc[m][ntl], a10, a11, a12, a13, B.z, B.w);
                }
            }
        }

        // -------- prepare next tile (before epilogue, to hide DRAM ramp) ----
        int havenext = (t + 1 < tend);
        int nseg = seg;
        if (havenext) {
            while (spre[nseg + 1] <= t + 1) nseg++;
            if (tid < TILE_M) {
                int l = nseg & 3, e = nseg >> 2;
                int R = 2 * l + 1;
                int r = (t + 1 - spre[nseg]) * TILE_M + tid;
                int rb = -1;
                if (r < scnt[e] * R) {
                    int atom = g_order[soff[e] + r / R];
                    rb = (atom * SH_DIM + l * l + r % R) * CIN;
                }
                rowb[(buf ^ 1) * TILE_M + tid] = rb;
            }
        }
        __syncthreads();   // rowbase visible; all warps past mainloop (B, Apan free)

        if (havenext && nseg != cur_seg) {
            const uint4* wp = g_wpack + nseg * 4096;
#pragma unroll
            for (int i = 0; i < 16; i++) Bs[tid + i * 256] = wp[tid + i * 256];
            cur_seg = nseg;
            __syncthreads();
        }

        if (havenext) {
            int* nbuf = rowb + (buf ^ 1) * TILE_M;
            int rb0 = nbuf[grow], rb1 = nbuf[64 + grow];
            cs0 = x + (rb0 < 0 ? 0 : rb0) + q * 4;  cz0 = rb0 < 0 ? 0 : 16;
            cs1 = x + (rb1 < 0 ? 0 : rb1) + q * 4;  cz1 = rb1 < 0 ? 0 : 16;
#pragma unroll
            for (int p = 0; p < NSTAGE - 1; p++) {
                uint32_t off = p * PAN_BYTES;
                cp16(d0 + off, cs0 + p * 16, cz0);
                cp16(d1 + off, cs1 + p * 16, cz1);
                asm volatile("cp.async.commit_group;" ::: "memory");
            }
        }

        // -------- epilogue for tile t (overlaps next tile's prefetch) -------
#pragma unroll
        for (int m = 0; m < 2; m++) {
            int rlo = (m == 0) ? rlo0 : rlo1;
            int rhi = (m == 0) ? rhi0 : rhi1;
#pragma unroll
            for (int ntl = 0; ntl < 8; ntl++) {
                int col = (ntb + ntl) * 8 + 2 * tig;
                if (rlo >= 0)
                    *(float2*)(out + rlo + col) =
                        make_float2(acc[m][ntl][0] * scale, acc[m][ntl][1] * scale);
                if (rhi >= 0)
                    *(float2*)(out + rhi + col) =
                        make_float2(acc[m][ntl][2] * scale, acc[m][ntl][3] * scale);
                acc[m][ntl][0] = 0.f; acc[m][ntl][1] = 0.f;
                acc[m][ntl][2] = 0.f; acc[m][ntl][3] = 0.f;
            }
        }
        seg = nseg;
    }
}

// ---------------- launch ----------------

extern "C" void kernel_launch(void* const* d_in, const int* in_sizes, int n_in,
                              void* d_out, int out_size) {
    const float* x = (const float*)d_in[0];   // [N, 16, 128]
    const float* y = (const float*)d_in[1];   // [N, 10]
    const float* w = (const float*)d_in[2];   // [10, 4, 128, 128]
    float* out = (float*)d_out;               // [N, 16, 128]

    cudaFuncSetAttribute(k_gemm, cudaFuncAttributeMaxDynamicSharedMemorySize,
                         SMEM_BYTES);

    k_init<<<1, 32>>>();
    k_hist<<<(N_ATOMS + 255) / 256, 256>>>(y);
    k_scan<<<1, 32>>>();
    k_scatter<<<(N_ATOMS + 255) / 256, 256>>>();
    k_wpack<<<(NSEG * 4096 + 255) / 256, 256>>>(w);
    k_gemm<<<GRID_PERS, 256, SMEM_BYTES>>>(x, out);
}